// round 2
// baseline (speedup 1.0000x reference)
#include <cuda_runtime.h>

// CFConv (SchNet) fused kernel, fp32 with packed f32x2 FMA (Blackwell FFMA2).
// Shapes: B=16, N=256, NBH=255, G=50, F=128.
// d_in: 0:x 1:r_ij(unused) 2:neighbors 3:pairwise_mask 4:f_ij
//       5:Wf1 6:bf1 7:Wf2 8:bf2 9:Win 10:Wout 11:bout
// out: float32 [16,256,128]

#define BN_TOTAL 4096      // B*N
#define FDIM 128
#define GDIM 50
#define NBHC 255
#define NPAD 256
#define CHUNK 64
#define NCHUNK 4
#define H1S 132            // padded row stride (floats) to dodge smem bank conflicts

typedef unsigned long long u64;

__device__ float g_y[BN_TOTAL * FDIM];      // x @ Win
__device__ float g_ypre[BN_TOTAL * FDIM];   // aggregated pre-output

__device__ __forceinline__ float sspf(float v) {
    // shifted softplus: softplus(v) - ln(2), numerically stable
    return fmaxf(v, 0.0f) + log1pf(__expf(-fabsf(v))) - 0.69314718055994530942f;
}

// ---- packed f32x2 helpers (SASS FFMA2 — only reachable via explicit PTX) ----
__device__ __forceinline__ u64 pk2(float lo, float hi) {
    u64 r; asm("mov.b64 %0, {%1, %2};" : "=l"(r) : "f"(lo), "f"(hi)); return r;
}
__device__ __forceinline__ void upk2(u64 v, float& lo, float& hi) {
    asm("mov.b64 {%0, %1}, %2;" : "=f"(lo), "=f"(hi) : "l"(v));
}
__device__ __forceinline__ u64 fma2(u64 a, u64 b, u64 c) {
    u64 d; asm("fma.rn.f32x2 %0, %1, %2, %3;" : "=l"(d) : "l"(a), "l"(b), "l"(c)); return d;
}
__device__ __forceinline__ u64 add2(u64 a, u64 b) {
    u64 d; asm("add.rn.f32x2 %0, %1, %2;" : "=l"(d) : "l"(a), "l"(b)); return d;
}
__device__ __forceinline__ u64 mul2(u64 a, u64 b) {
    u64 d; asm("mul.rn.f32x2 %0, %1, %2;" : "=l"(d) : "l"(a), "l"(b)); return d;
}

// ---------------------------------------------------------------------------
// Kernel 1: g_y = x @ Win        (4096 x 128) = (4096 x 128)(128 x 128)
// grid 256 blocks x 256 threads; block handles 16 rows.
// ---------------------------------------------------------------------------
__global__ __launch_bounds__(256) void k_in2f(const float* __restrict__ x,
                                              const float* __restrict__ Win) {
    extern __shared__ float sm[];
    float* Ws = sm;                    // 128*128
    float* xs = sm + FDIM * FDIM;      // 16*H1S
    const int t = threadIdx.x;
    const int row0 = blockIdx.x * 16;

    for (int i = t * 4; i < FDIM * FDIM; i += 1024)
        *(float4*)(Ws + i) = *(const float4*)(Win + i);
    for (int i = t * 4; i < 16 * FDIM; i += 1024) {
        int r = i >> 7, c = i & 127;
        *(float4*)(xs + r * H1S + c) = *(const float4*)(x + (row0 + r) * FDIM + c);
    }
    __syncthreads();

    const int r = t >> 4;
    const int c0 = (t & 15) * 8;
    u64 acc[4] = {0, 0, 0, 0};
#pragma unroll 4
    for (int d = 0; d < FDIM; d++) {
        u64 a2 = pk2(xs[r * H1S + d], xs[r * H1S + d]);
        const u64* wp = (const u64*)(Ws + d * FDIM + c0);
#pragma unroll
        for (int j = 0; j < 4; j++) acc[j] = fma2(a2, wp[j], acc[j]);
    }
    u64* o = (u64*)(g_y + (row0 + r) * FDIM + c0);
#pragma unroll
    for (int j = 0; j < 4; j++) o[j] = acc[j];
}

// ---------------------------------------------------------------------------
// Kernel 2: fused filter-net + gather + masked aggregate, one CTA per (b,n).
//   H1 = ssp(f_ij[b,n] @ Wf1 + bf1)                 [255 x 128]  (in smem)
//   W2 = H1 @ Wf2 + bf2                              [255 x 128]  (in regs)
//   g_ypre[b,n,:] = sum_k mask[k] * W2[k,:] * g_y[b, nbr[k], :]
// grid 4096 blocks x 256 threads. 256 = 16 row-threads x 16 col-threads;
// each thread owns a 4x8 micro-tile of the 64-row chunk.
// ---------------------------------------------------------------------------
__global__ __launch_bounds__(256) void k_main(const float* __restrict__ f_ij,
                                              const int* __restrict__ neighbors,
                                              const float* __restrict__ pmask,
                                              const float* __restrict__ Wf1,
                                              const float* __restrict__ bf1,
                                              const float* __restrict__ Wf2,
                                              const float* __restrict__ bf2) {
    extern __shared__ float sm[];
    float* Wf1_s  = sm;                         // 50*128   = 6400
    float* Wf2_s  = Wf1_s + GDIM * FDIM;        // 128*128  = 16384
    float* bf1_s  = Wf2_s + FDIM * FDIM;        // 128
    float* bf2_s  = bf1_s + FDIM;               // 128
    float* mask_s = bf2_s + FDIM;               // 256
    int*   nbr_s  = (int*)(mask_s + NPAD);      // 256
    float* f_s    = (float*)(nbr_s + NPAD);     // 64*50    = 3200
    float* H1_s   = f_s + CHUNK * GDIM;         // 64*132   = 8448

    const int t  = threadIdx.x;
    const int bn = blockIdx.x;
    const int b  = bn >> 8;

    // ---- phase 0: weights / biases / neighbor metadata ----
    for (int i = t * 4; i < GDIM * FDIM; i += 1024)
        *(float4*)(Wf1_s + i) = *(const float4*)(Wf1 + i);
    for (int i = t * 4; i < FDIM * FDIM; i += 1024)
        *(float4*)(Wf2_s + i) = *(const float4*)(Wf2 + i);
    if (t < FDIM) {
        bf1_s[t] = bf1[t];
        bf2_s[t] = bf2[t];
    }
    if (t < NBHC) {
        nbr_s[t]  = neighbors[bn * NBHC + t];
        mask_s[t] = pmask[bn * NBHC + t];
    } else if (t < NPAD) {
        nbr_s[t]  = 0;
        mask_s[t] = 0.0f;   // padded neighbor row contributes nothing
    }
    __syncthreads();

    const int tc  = t & 15;
    const int tr  = t >> 4;
    const int tr4 = tr * 4;
    const int c0  = tc * 8;

    u64 b1p[4], bbp[4];
#pragma unroll
    for (int j = 0; j < 4; j++) {
        b1p[j] = pk2(bf1_s[c0 + 2 * j], bf1_s[c0 + 2 * j + 1]);
        bbp[j] = pk2(bf2_s[c0 + 2 * j], bf2_s[c0 + 2 * j + 1]);
    }

    u64 acc[4] = {0, 0, 0, 0};
    const float* fbase = f_ij + (long)bn * (NBHC * GDIM);

    for (int c = 0; c < NCHUNK; c++) {
        __syncthreads();  // previous chunk's consumers of f_s/H1_s are done
        // ---- load f chunk (contiguous 64*50 floats; zero-pad the tail) ----
        const int base  = c * (CHUNK * GDIM);
        const int limit = NBHC * GDIM - base;
        for (int i = t; i < CHUNK * GDIM; i += 256)
            f_s[i] = (i < limit) ? fbase[base + i] : 0.0f;
        __syncthreads();

        // ---- GEMM1: c1[4][4 pairs] = f_chunk @ Wf1 ----
        u64 c1[4][4];
#pragma unroll
        for (int i = 0; i < 4; i++)
#pragma unroll
            for (int j = 0; j < 4; j++) c1[i][j] = 0;

#pragma unroll 2
        for (int k = 0; k < GDIM; k++) {
            u64 a2[4];
#pragma unroll
            for (int i = 0; i < 4; i++) {
                float a = f_s[(tr4 + i) * GDIM + k];
                a2[i] = pk2(a, a);
            }
            const u64* wp = (const u64*)(Wf1_s + k * FDIM + c0);
            u64 w[4] = {wp[0], wp[1], wp[2], wp[3]};
#pragma unroll
            for (int i = 0; i < 4; i++)
#pragma unroll
                for (int j = 0; j < 4; j++)
                    c1[i][j] = fma2(a2[i], w[j], c1[i][j]);
        }

        // ---- bias + ssp -> H1 smem ----
#pragma unroll
        for (int i = 0; i < 4; i++) {
            int row = tr4 + i;
            u64* hp = (u64*)(H1_s + row * H1S + c0);
#pragma unroll
            for (int j = 0; j < 4; j++) {
                float lo, hi;
                upk2(add2(c1[i][j], b1p[j]), lo, hi);
                hp[j] = pk2(sspf(lo), sspf(hi));
            }
        }
        __syncthreads();

        // ---- GEMM2: c2[4][4 pairs] = H1_chunk @ Wf2 ----
        u64 c2[4][4];
#pragma unroll
        for (int i = 0; i < 4; i++)
#pragma unroll
            for (int j = 0; j < 4; j++) c2[i][j] = 0;

#pragma unroll 4
        for (int k = 0; k < FDIM; k++) {
            u64 a2[4];
#pragma unroll
            for (int i = 0; i < 4; i++) {
                float a = H1_s[(tr4 + i) * H1S + k];
                a2[i] = pk2(a, a);
            }
            const u64* wp = (const u64*)(Wf2_s + k * FDIM + c0);
            u64 w[4] = {wp[0], wp[1], wp[2], wp[3]};
#pragma unroll
            for (int i = 0; i < 4; i++)
#pragma unroll
                for (int j = 0; j < 4; j++)
                    c2[i][j] = fma2(a2[i], w[j], c2[i][j]);
        }

        // ---- epilogue: gather y[nbr], mask, accumulate over rows ----
#pragma unroll
        for (int i = 0; i < 4; i++) {
            int row  = c * CHUNK + tr4 + i;
            float m  = mask_s[row];
            u64 m2   = pk2(m, m);
            int nbr  = nbr_s[row];
            const u64* yrow = (const u64*)(g_y + (((b << 8) + nbr) * FDIM) + c0);
            u64 y[4] = {yrow[0], yrow[1], yrow[2], yrow[3]};
#pragma unroll
            for (int j = 0; j < 4; j++) {
                u64 w2m = mul2(add2(c2[i][j], bbp[j]), m2);
                acc[j]  = fma2(w2m, y[j], acc[j]);
            }
        }
    }

    // ---- reduce acc across the 16 row-thread groups ----
    __syncthreads();
    float* red = H1_s;  // reuse (needs 16*128 floats, have 64*132)
#pragma unroll
    for (int j = 0; j < 4; j++) {
        float lo, hi;
        upk2(acc[j], lo, hi);
        red[tr * FDIM + c0 + 2 * j]     = lo;
        red[tr * FDIM + c0 + 2 * j + 1] = hi;
    }
    __syncthreads();
    if (t < FDIM) {
        float s = 0.0f;
#pragma unroll
        for (int i = 0; i < 16; i++) s += red[i * FDIM + t];
        g_ypre[bn * FDIM + t] = s;
    }
}

// ---------------------------------------------------------------------------
// Kernel 3: out = ssp(g_ypre @ Wout + bout)
// grid 256 blocks x 256 threads; block handles 16 rows.
// ---------------------------------------------------------------------------
__global__ __launch_bounds__(256) void k_out(const float* __restrict__ Wout,
                                             const float* __restrict__ bout,
                                             float* __restrict__ out) {
    extern __shared__ float sm[];
    float* Ws = sm;                     // 128*128
    float* xs = Ws + FDIM * FDIM;       // 16*H1S
    float* bs = xs + 16 * H1S;          // 128
    const int t = threadIdx.x;
    const int row0 = blockIdx.x * 16;

    for (int i = t * 4; i < FDIM * FDIM; i += 1024)
        *(float4*)(Ws + i) = *(const float4*)(Wout + i);
    for (int i = t * 4; i < 16 * FDIM; i += 1024) {
        int r = i >> 7, c = i & 127;
        *(float4*)(xs + r * H1S + c) = *(const float4*)(g_ypre + (row0 + r) * FDIM + c);
    }
    if (t < FDIM) bs[t] = bout[t];
    __syncthreads();

    const int r = t >> 4;
    const int c0 = (t & 15) * 8;
    u64 acc[4];
#pragma unroll
    for (int j = 0; j < 4; j++) acc[j] = pk2(bs[c0 + 2 * j], bs[c0 + 2 * j + 1]);
#pragma unroll 4
    for (int d = 0; d < FDIM; d++) {
        u64 a2 = pk2(xs[r * H1S + d], xs[r * H1S + d]);
        const u64* wp = (const u64*)(Ws + d * FDIM + c0);
#pragma unroll
        for (int j = 0; j < 4; j++) acc[j] = fma2(a2, wp[j], acc[j]);
    }
    float* o = out + (row0 + r) * FDIM + c0;
#pragma unroll
    for (int j = 0; j < 4; j++) {
        float lo, hi;
        upk2(acc[j], lo, hi);
        o[2 * j]     = sspf(lo);
        o[2 * j + 1] = sspf(hi);
    }
}

// ---------------------------------------------------------------------------
extern "C" void kernel_launch(void* const* d_in, const int* in_sizes, int n_in,
                              void* d_out, int out_size) {
    const float* x         = (const float*)d_in[0];
    // d_in[1] = r_ij, unused by the reference
    const int*   neighbors = (const int*)d_in[2];
    const float* pmask     = (const float*)d_in[3];
    const float* f_ij      = (const float*)d_in[4];
    const float* Wf1       = (const float*)d_in[5];
    const float* bf1       = (const float*)d_in[6];
    const float* Wf2       = (const float*)d_in[7];
    const float* bf2       = (const float*)d_in[8];
    const float* Win       = (const float*)d_in[9];
    const float* Wout      = (const float*)d_in[10];
    const float* bout      = (const float*)d_in[11];

    const int smem1 = (FDIM * FDIM + 16 * H1S) * 4;                 // ~74 KB
    const int smem2 = (GDIM * FDIM + FDIM * FDIM + 2 * FDIM + 2 * NPAD +
                       CHUNK * GDIM + CHUNK * H1S) * 4;             // ~138 KB
    const int smem3 = (FDIM * FDIM + 16 * H1S + FDIM) * 4;          // ~75 KB

    cudaFuncSetAttribute(k_in2f, cudaFuncAttributeMaxDynamicSharedMemorySize, smem1);
    cudaFuncSetAttribute(k_main, cudaFuncAttributeMaxDynamicSharedMemorySize, smem2);
    cudaFuncSetAttribute(k_out,  cudaFuncAttributeMaxDynamicSharedMemorySize, smem3);

    k_in2f<<<BN_TOTAL / 16, 256, smem1>>>(x, Win);
    k_main<<<BN_TOTAL, 256, smem2>>>(f_ij, neighbors, pmask, Wf1, bf1, Wf2, bf2);
    k_out<<<BN_TOTAL / 16, 256, smem3>>>(Wout, bout, (float*)d_out);
}

// round 8
// speedup vs baseline: 1.4547x; 1.4547x over previous
#include <cuda_runtime.h>
#include <cstdint>

// CFConv (SchNet): mma.sync tf32 fused kernel (sm_100-safe, no tcgen05).
// Shapes: B=16, N=256, NBH=255, G=50, F=128.
// d_in: 0:x 1:r_ij(unused) 2:neighbors 3:pairwise_mask 4:f_ij
//       5:Wf1 6:bf1 7:Wf2 8:bf2 9:Win 10:Wout 11:bout

#define BN_TOTAL 4096
#define FDIM 128
#define GDIM 50
#define NBHC 255
#define H1S 132
#define BN_PER_CTA 4
#define MAIN_GRID (BN_TOTAL / BN_PER_CTA)

// fragment-permuted A layouts: per 16-row tile, u = row16*4 + (k&3), kk = k>>2
#define K1P 18                    // GEMM1: 16 kk + 2 pad (K=64)
#define A1_TILE (64 * K1P)        // 1152 floats
#define K2P 34                    // GEMM2: 32 kk + 2 pad (K=128)
#define A2_TILE (64 * K2P)        // 2176 floats
#define RB1 258                   // B1 per-thread row: 8 s * 32 + 2 pad
#define RB2 514                   // B2 per-thread row: 16 s * 32 + 2 pad

// float offsets in k_main smem
#define O_A1   0
#define O_A2   (O_A1 + 8 * A1_TILE)     // 9216
#define O_B1   (O_A2 + 8 * A2_TILE)     // 26624
#define O_B2   (O_B1 + 32 * RB1)        // 34880
#define O_BF1  (O_B2 + 32 * RB2)        // 51328
#define O_BF2  (O_BF1 + 128)
#define O_MASK (O_BF2 + 128)
#define O_NBR  (O_MASK + 128)
#define O_RED  (O_NBR + 128)
#define SMEM_MAIN ((O_RED + 512) * 4)   // 209408 B

typedef unsigned long long u64;

__device__ float g_y[BN_TOTAL * FDIM];
__device__ float g_ypre[BN_TOTAL * FDIM];
__device__ float g_B1img[32 * RB1];     // Wf1 fragment-permuted (tf32)
__device__ float g_B2img[32 * RB2];     // Wf2 fragment-permuted (tf32)

__device__ __forceinline__ float sspf(float v) {
    return fmaxf(v, 0.0f) + log1pf(__expf(-fabsf(v))) - 0.69314718055994530942f;
}
// tf32 cvt: destination must be a .b32 register (ptxas rejects .f32 dst).
__device__ __forceinline__ float to_tf32(float v) {
    uint32_t r; asm("cvt.rna.tf32.f32 %0, %1;" : "=r"(r) : "f"(v));
    return __uint_as_float(r);
}

// ---- packed f32x2 helpers (small kernels) ----
__device__ __forceinline__ u64 pk2(float lo, float hi) {
    u64 r; asm("mov.b64 %0, {%1, %2};" : "=l"(r) : "f"(lo), "f"(hi)); return r;
}
__device__ __forceinline__ void upk2(u64 v, float& lo, float& hi) {
    asm("mov.b64 {%0, %1}, %2;" : "=f"(lo), "=f"(hi) : "l"(v));
}
__device__ __forceinline__ u64 fma2(u64 a, u64 b, u64 c) {
    u64 d; asm("fma.rn.f32x2 %0, %1, %2, %3;" : "=l"(d) : "l"(a), "l"(b), "l"(c)); return d;
}

// m16n8k8 tf32 MMA. a0=(g,c) a1=(g+8,c) a2=(g,c+4) a3=(g+8,c+4); b0=(c,g) b1=(c+4,g)
__device__ __forceinline__ void mma8(float d[4], float2 alo, float2 ahi, float2 b) {
    asm volatile(
        "mma.sync.aligned.m16n8k8.row.col.f32.tf32.tf32.f32 "
        "{%0,%1,%2,%3}, {%4,%5,%6,%7}, {%8,%9}, {%0,%1,%2,%3};"
        : "+f"(d[0]), "+f"(d[1]), "+f"(d[2]), "+f"(d[3])
        : "r"(__float_as_uint(alo.x)), "r"(__float_as_uint(ahi.x)),
          "r"(__float_as_uint(alo.y)), "r"(__float_as_uint(ahi.y)),
          "r"(__float_as_uint(b.x)),   "r"(__float_as_uint(b.y)));
}

// ---------------------------------------------------------------------------
// k_prep: fragment-permute + tf32-round both filter weights into global images.
// B layout: row u2 = thread lane (g*4+c); entry [s][ntg][j] at u2*RB + s*32 + ntg*2 + j
// holds W[k][n] with k = s*8 + c + 4j, n = ntg*8 + g.
// ---------------------------------------------------------------------------
__global__ void k_prep(const float* __restrict__ Wf1, const float* __restrict__ Wf2) {
    int t = blockIdx.x * blockDim.x + threadIdx.x;
    int stride = gridDim.x * blockDim.x;
#pragma unroll 1
    for (int i = t; i < 32 * 8 * 16 * 2; i += stride) {
        int j   = i & 1;
        int ntg = (i >> 1) & 15;
        int s   = (i >> 5) & 7;
        int u2  = i >> 8;
        int c = u2 & 3, g = u2 >> 2;
        int k = s * 8 + c + 4 * j;
        int n = ntg * 8 + g;
        float v = (k < GDIM) ? Wf1[k * FDIM + n] : 0.0f;
        g_B1img[u2 * RB1 + s * 32 + ntg * 2 + j] = to_tf32(v);
    }
#pragma unroll 1
    for (int i = t; i < 32 * 16 * 16 * 2; i += stride) {
        int j   = i & 1;
        int ntg = (i >> 1) & 15;
        int s   = (i >> 5) & 15;
        int u2  = i >> 9;
        int c = u2 & 3, g = u2 >> 2;
        int k = s * 8 + c + 4 * j;
        int n = ntg * 8 + g;
        g_B2img[u2 * RB2 + s * 32 + ntg * 2 + j] = to_tf32(Wf2[k * FDIM + n]);
    }
}

// ---------------------------------------------------------------------------
// k_in2f: g_y = x @ Win (FFMA2)
// ---------------------------------------------------------------------------
__global__ __launch_bounds__(256) void k_in2f(const float* __restrict__ x,
                                              const float* __restrict__ Win) {
    extern __shared__ float sm[];
    float* Ws = sm;
    float* xs = sm + FDIM * FDIM;
    const int t = threadIdx.x;
    const int row0 = blockIdx.x * 16;
    for (int i = t * 4; i < FDIM * FDIM; i += 1024)
        *(float4*)(Ws + i) = *(const float4*)(Win + i);
    for (int i = t * 4; i < 16 * FDIM; i += 1024) {
        int r = i >> 7, c = i & 127;
        *(float4*)(xs + r * H1S + c) = *(const float4*)(x + (row0 + r) * FDIM + c);
    }
    __syncthreads();
    const int r = t >> 4;
    const int c0 = (t & 15) * 8;
    u64 acc[4] = {0, 0, 0, 0};
#pragma unroll 4
    for (int d = 0; d < FDIM; d++) {
        u64 a2 = pk2(xs[r * H1S + d], xs[r * H1S + d]);
        const u64* wp = (const u64*)(Ws + d * FDIM + c0);
#pragma unroll
        for (int j = 0; j < 4; j++) acc[j] = fma2(a2, wp[j], acc[j]);
    }
    u64* o = (u64*)(g_y + (row0 + r) * FDIM + c0);
#pragma unroll
    for (int j = 0; j < 4; j++) o[j] = acc[j];
}

// ---------------------------------------------------------------------------
// k_main: tf32 mma.sync fused filter-net + gather + masked aggregate.
// grid MAIN_GRID x 256. 8 warps = 4 wrow x 2 wcol; warp tile 32 rows x 64 cols.
// ---------------------------------------------------------------------------
__global__ __launch_bounds__(256, 1) void k_main(const float* __restrict__ f_ij,
                                                 const int* __restrict__ neighbors,
                                                 const float* __restrict__ pmask,
                                                 const float* __restrict__ bf1,
                                                 const float* __restrict__ bf2) {
    extern __shared__ float sm[];
    const int t = threadIdx.x;
    const int w = t >> 5, lane = t & 31;
    const int g = lane >> 2, c = lane & 3;
    const int wrow = w >> 1, wcol = w & 1;

    float* bf1s  = sm + O_BF1;
    float* bf2s  = sm + O_BF2;
    float* masks = sm + O_MASK;
    int*   nbrs  = (int*)(sm + O_NBR);
    float* red   = sm + O_RED;

    // one-time: weight fragments + biases
    for (int i = t * 2; i < 32 * RB1; i += 512)
        *(float2*)(sm + O_B1 + i) = *(const float2*)(g_B1img + i);
    for (int i = t * 2; i < 32 * RB2; i += 512)
        *(float2*)(sm + O_B2 + i) = *(const float2*)(g_B2img + i);
    if (t < FDIM) { bf1s[t] = bf1[t]; bf2s[t] = bf2[t]; }
    __syncthreads();

#pragma unroll 1
    for (int rep = 0; rep < BN_PER_CTA; rep++) {
        const int bn = blockIdx.x * BN_PER_CTA + rep;
        const int b  = bn >> 8;
        const float* fb = f_ij + (long)bn * (NBHC * GDIM);

        float acc[16];
#pragma unroll
        for (int j = 0; j < 16; j++) acc[j] = 0.0f;

#pragma unroll 1
        for (int ch = 0; ch < 2; ch++) {
            __syncthreads();   // prior consumers of A1/A2/mask done

            // ---- stage A1 chunk (128 rows x 64 k, fragment-permuted, tf32) ----
#pragma unroll 1
            for (int i = t; i < 128 * 64; i += 256) {
                int row = i >> 6, k = i & 63;
                int grow = ch * 128 + row;
                float v = (k < GDIM && grow < NBHC) ? fb[grow * GDIM + k] : 0.0f;
                sm[O_A1 + (row >> 4) * A1_TILE +
                   (((row & 15) << 2) + (k & 3)) * K1P + (k >> 2)] = to_tf32(v);
            }
            if (t < 128) {
                int grow = ch * 128 + t;
                masks[t] = (grow < NBHC) ? pmask[bn * NBHC + grow] : 0.0f;
                nbrs[t]  = (grow < NBHC) ? neighbors[bn * NBHC + grow] : 0;
            }
            __syncthreads();

            // ---- GEMM1: C1 = A1 @ B1 (K=64) ----
            float C1[2][8][4];
#pragma unroll
            for (int mt = 0; mt < 2; mt++)
#pragma unroll
                for (int nt = 0; nt < 8; nt++)
#pragma unroll
                    for (int q = 0; q < 4; q++) C1[mt][nt][q] = 0.0f;

#pragma unroll
            for (int s = 0; s < 8; s++) {
                float2 alo[2], ahi[2];
#pragma unroll
                for (int mt = 0; mt < 2; mt++) {
                    const float* tile = sm + O_A1 + (wrow * 2 + mt) * A1_TILE;
                    alo[mt] = *(const float2*)(tile + lane * K1P + 2 * s);
                    ahi[mt] = *(const float2*)(tile + (lane + 32) * K1P + 2 * s);
                }
                const float* brow = sm + O_B1 + lane * RB1 + s * 32 + wcol * 16;
                float2 bf[8];
#pragma unroll
                for (int nt = 0; nt < 8; nt++) bf[nt] = *(const float2*)(brow + nt * 2);
#pragma unroll
                for (int nt = 0; nt < 8; nt++)
#pragma unroll
                    for (int mt = 0; mt < 2; mt++)
                        mma8(C1[mt][nt], alo[mt], ahi[mt], bf[nt]);
            }

            // ---- epilogue 1: bias + ssp -> A2 fragment-permuted (tf32) ----
#pragma unroll
            for (int mt = 0; mt < 2; mt++) {
                float* a2t = sm + O_A2 + (wrow * 2 + mt) * A2_TILE;
#pragma unroll
                for (int nt = 0; nt < 8; nt++) {
                    int col = wcol * 64 + nt * 8 + 2 * c;
                    float h0 = to_tf32(sspf(C1[mt][nt][0] + bf1s[col]));
                    float h1 = to_tf32(sspf(C1[mt][nt][1] + bf1s[col + 1]));
                    float h2 = to_tf32(sspf(C1[mt][nt][2] + bf1s[col]));
                    float h3 = to_tf32(sspf(C1[mt][nt][3] + bf1s[col + 1]));
                    int u0 = (g << 2)       + (col & 3);
                    int u1 = (g << 2)       + ((col + 1) & 3);
                    int u2 = ((g + 8) << 2) + (col & 3);
                    int u3 = ((g + 8) << 2) + ((col + 1) & 3);
                    a2t[u0 * K2P + (col >> 2)]       = h0;
                    a2t[u1 * K2P + ((col + 1) >> 2)] = h1;
                    a2t[u2 * K2P + (col >> 2)]       = h2;
                    a2t[u3 * K2P + ((col + 1) >> 2)] = h3;
                }
            }
            __syncthreads();

            // ---- GEMM2: C2 = A2 @ B2 (K=128) ----
            float C2[2][8][4];
#pragma unroll
            for (int mt = 0; mt < 2; mt++)
#pragma unroll
                for (int nt = 0; nt < 8; nt++)
#pragma unroll
                    for (int q = 0; q < 4; q++) C2[mt][nt][q] = 0.0f;

#pragma unroll
            for (int s = 0; s < 16; s++) {
                float2 alo[2], ahi[2];
#pragma unroll
                for (int mt = 0; mt < 2; mt++) {
                    const float* tile = sm + O_A2 + (wrow * 2 + mt) * A2_TILE;
                    alo[mt] = *(const float2*)(tile + lane * K2P + 2 * s);
                    ahi[mt] = *(const float2*)(tile + (lane + 32) * K2P + 2 * s);
                }
                const float* brow = sm + O_B2 + lane * RB2 + s * 32 + wcol * 16;
                float2 bf[8];
#pragma unroll
                for (int nt = 0; nt < 8; nt++) bf[nt] = *(const float2*)(brow + nt * 2);
#pragma unroll
                for (int nt = 0; nt < 8; nt++)
#pragma unroll
                    for (int mt = 0; mt < 2; mt++)
                        mma8(C2[mt][nt], alo[mt], ahi[mt], bf[nt]);
            }

            // ---- epilogue 2: bias, mask, gather y[nbr], accumulate ----
#pragma unroll
            for (int mt = 0; mt < 2; mt++) {
                int r0 = wrow * 32 + mt * 16 + g;
                float m0 = masks[r0], m1 = masks[r0 + 8];
                int   n0 = nbrs[r0],  n1 = nbrs[r0 + 8];
                const float* y0 = g_y + ((((b << 8) + n0)) << 7);
                const float* y1 = g_y + ((((b << 8) + n1)) << 7);
#pragma unroll
                for (int nt = 0; nt < 8; nt++) {
                    int col = wcol * 64 + nt * 8 + 2 * c;
                    float2 yv0 = *(const float2*)(y0 + col);
                    float2 yv1 = *(const float2*)(y1 + col);
                    float w00 = C2[mt][nt][0] + bf2s[col];
                    float w01 = C2[mt][nt][1] + bf2s[col + 1];
                    float w10 = C2[mt][nt][2] + bf2s[col];
                    float w11 = C2[mt][nt][3] + bf2s[col + 1];
                    acc[nt * 2]     = fmaf(m0 * w00, yv0.x, fmaf(m1 * w10, yv1.x, acc[nt * 2]));
                    acc[nt * 2 + 1] = fmaf(m0 * w01, yv0.y, fmaf(m1 * w11, yv1.y, acc[nt * 2 + 1]));
                }
            }
        }

        // ---- reduce over g (lanes stride-4) then over wrow warps via smem ----
#pragma unroll
        for (int j = 0; j < 16; j++) {
            float v = acc[j];
            v += __shfl_xor_sync(0xffffffffu, v, 4);
            v += __shfl_xor_sync(0xffffffffu, v, 8);
            v += __shfl_xor_sync(0xffffffffu, v, 16);
            acc[j] = v;
        }
        __syncthreads();   // red region (fresh each rep)
        if (g == 0) {
#pragma unroll
            for (int nt = 0; nt < 8; nt++) {
                int col = wcol * 64 + nt * 8 + 2 * c;
                red[wrow * FDIM + col]     = acc[nt * 2];
                red[wrow * FDIM + col + 1] = acc[nt * 2 + 1];
            }
        }
        __syncthreads();
        if (t < FDIM) {
            g_ypre[bn * FDIM + t] =
                red[t] + red[FDIM + t] + red[2 * FDIM + t] + red[3 * FDIM + t];
        }
    }
}

// ---------------------------------------------------------------------------
// k_out: out = ssp(g_ypre @ Wout + bout) (FFMA2)
// ---------------------------------------------------------------------------
__global__ __launch_bounds__(256) void k_out(const float* __restrict__ Wout,
                                             const float* __restrict__ bout,
                                             float* __restrict__ out) {
    extern __shared__ float sm[];
    float* Ws = sm;
    float* xs = Ws + FDIM * FDIM;
    float* bs = xs + 16 * H1S;
    const int t = threadIdx.x;
    const int row0 = blockIdx.x * 16;
    for (int i = t * 4; i < FDIM * FDIM; i += 1024)
        *(float4*)(Ws + i) = *(const float4*)(Wout + i);
    for (int i = t * 4; i < 16 * FDIM; i += 1024) {
        int r = i >> 7, c = i & 127;
        *(float4*)(xs + r * H1S + c) = *(const float4*)(g_ypre + (row0 + r) * FDIM + c);
    }
    if (t < FDIM) bs[t] = bout[t];
    __syncthreads();
    const int r = t >> 4;
    const int c0 = (t & 15) * 8;
    u64 acc[4];
#pragma unroll
    for (int j = 0; j < 4; j++) acc[j] = pk2(bs[c0 + 2 * j], bs[c0 + 2 * j + 1]);
#pragma unroll 4
    for (int d = 0; d < FDIM; d++) {
        u64 a2 = pk2(xs[r * H1S + d], xs[r * H1S + d]);
        const u64* wp = (const u64*)(Ws + d * FDIM + c0);
#pragma unroll
        for (int j = 0; j < 4; j++) acc[j] = fma2(a2, wp[j], acc[j]);
    }
    float* o = out + (row0 + r) * FDIM + c0;
#pragma unroll
    for (int j = 0; j < 4; j++) {
        float lo, hi;
        upk2(acc[j], lo, hi);
        o[2 * j]     = sspf(lo);
        o[2 * j + 1] = sspf(hi);
    }
}

// ---------------------------------------------------------------------------
extern "C" void kernel_launch(void* const* d_in, const int* in_sizes, int n_in,
                              void* d_out, int out_size) {
    const float* x         = (const float*)d_in[0];
    const int*   neighbors = (const int*)d_in[2];
    const float* pmask     = (const float*)d_in[3];
    const float* f_ij      = (const float*)d_in[4];
    const float* Wf1       = (const float*)d_in[5];
    const float* bf1       = (const float*)d_in[6];
    const float* Wf2       = (const float*)d_in[7];
    const float* bf2       = (const float*)d_in[8];
    const float* Win       = (const float*)d_in[9];
    const float* Wout      = (const float*)d_in[10];
    const float* bout      = (const float*)d_in[11];

    const int smem1 = (FDIM * FDIM + 16 * H1S) * 4;
    const int smem3 = (FDIM * FDIM + 16 * H1S + FDIM) * 4;

    cudaFuncSetAttribute(k_in2f, cudaFuncAttributeMaxDynamicSharedMemorySize, smem1);
    cudaFuncSetAttribute(k_main, cudaFuncAttributeMaxDynamicSharedMemorySize, SMEM_MAIN);
    cudaFuncSetAttribute(k_out,  cudaFuncAttributeMaxDynamicSharedMemorySize, smem3);

    k_prep<<<32, 256>>>(Wf1, Wf2);
    k_in2f<<<BN_TOTAL / 16, 256, smem1>>>(x, Win);
    k_main<<<MAIN_GRID, 256, SMEM_MAIN>>>(f_ij, neighbors, pmask, bf1, bf2);
    k_out<<<BN_TOTAL / 16, 256, smem3>>>(Wout, bout, (float*)d_out);
}

// round 9
// speedup vs baseline: 2.0689x; 1.4222x over previous
#include <cuda_runtime.h>
#include <cstdint>

// CFConv (SchNet): mma.sync tf32 fused kernel, 512-thread k_main (16 warps).
// Shapes: B=16, N=256, NBH=255, G=50, F=128.
// d_in: 0:x 1:r_ij(unused) 2:neighbors 3:pairwise_mask 4:f_ij
//       5:Wf1 6:bf1 7:Wf2 8:bf2 9:Win 10:Wout 11:bout

#define BN_TOTAL 4096
#define FDIM 128
#define GDIM 50
#define NBHC 255
#define H1S 132
#define BN_PER_CTA 4
#define MAIN_GRID (BN_TOTAL / BN_PER_CTA)

// fragment-permuted A layouts: per 16-row tile, u = row16*4 + (k&3), kk = k>>2
#define K1P 18                    // GEMM1: 16 kk + 2 pad (K=64)
#define A1_TILE (64 * K1P)        // 1152 floats
#define K2P 34                    // GEMM2: 32 kk + 2 pad (K=128)
#define A2_TILE (64 * K2P)        // 2176 floats
#define RB1 258                   // B1 per-thread row: 8 s * 32 + 2 pad
#define RB2 514                   // B2 per-thread row: 16 s * 32 + 2 pad

// float offsets in k_main smem
#define O_A1   0
#define O_A2   (O_A1 + 8 * A1_TILE)     // 9216
#define O_B1   (O_A2 + 8 * A2_TILE)     // 26624
#define O_B2   (O_B1 + 32 * RB1)        // 34880
#define O_BF1  (O_B2 + 32 * RB2)        // 51328
#define O_BF2  (O_BF1 + 128)
#define O_MASK (O_BF2 + 128)
#define O_NBR  (O_MASK + 128)
#define O_RED  (O_NBR + 128)
#define SMEM_MAIN ((O_RED + 512) * 4)   // 209408 B

typedef unsigned long long u64;

__device__ float g_y[BN_TOTAL * FDIM];
__device__ float g_ypre[BN_TOTAL * FDIM];
__device__ float g_B1img[32 * RB1];     // Wf1 fragment-permuted (tf32)
__device__ float g_B2img[32 * RB2];     // Wf2 fragment-permuted (tf32)

__device__ __forceinline__ float sspf(float v) {
    return fmaxf(v, 0.0f) + log1pf(__expf(-fabsf(v))) - 0.69314718055994530942f;
}
// tf32 cvt: destination must be a .b32 register (ptxas rejects .f32 dst).
__device__ __forceinline__ float to_tf32(float v) {
    uint32_t r; asm("cvt.rna.tf32.f32 %0, %1;" : "=r"(r) : "f"(v));
    return __uint_as_float(r);
}

// ---- packed f32x2 helpers (small kernels) ----
__device__ __forceinline__ u64 pk2(float lo, float hi) {
    u64 r; asm("mov.b64 %0, {%1, %2};" : "=l"(r) : "f"(lo), "f"(hi)); return r;
}
__device__ __forceinline__ void upk2(u64 v, float& lo, float& hi) {
    asm("mov.b64 {%0, %1}, %2;" : "=f"(lo), "=f"(hi) : "l"(v));
}
__device__ __forceinline__ u64 fma2(u64 a, u64 b, u64 c) {
    u64 d; asm("fma.rn.f32x2 %0, %1, %2, %3;" : "=l"(d) : "l"(a), "l"(b), "l"(c)); return d;
}

// m16n8k8 tf32 MMA. a0=(g,c) a1=(g+8,c) a2=(g,c+4) a3=(g+8,c+4); b0=(c,g) b1=(c+4,g)
__device__ __forceinline__ void mma8(float d[4], float2 alo, float2 ahi, float2 b) {
    asm volatile(
        "mma.sync.aligned.m16n8k8.row.col.f32.tf32.tf32.f32 "
        "{%0,%1,%2,%3}, {%4,%5,%6,%7}, {%8,%9}, {%0,%1,%2,%3};"
        : "+f"(d[0]), "+f"(d[1]), "+f"(d[2]), "+f"(d[3])
        : "r"(__float_as_uint(alo.x)), "r"(__float_as_uint(ahi.x)),
          "r"(__float_as_uint(alo.y)), "r"(__float_as_uint(ahi.y)),
          "r"(__float_as_uint(b.x)),   "r"(__float_as_uint(b.y)));
}

// ---------------------------------------------------------------------------
// k_prep: fragment-permute + tf32-round both filter weights into global images.
// ---------------------------------------------------------------------------
__global__ void k_prep(const float* __restrict__ Wf1, const float* __restrict__ Wf2) {
    int t = blockIdx.x * blockDim.x + threadIdx.x;
    int stride = gridDim.x * blockDim.x;
#pragma unroll 1
    for (int i = t; i < 32 * 8 * 16 * 2; i += stride) {
        int j   = i & 1;
        int ntg = (i >> 1) & 15;
        int s   = (i >> 5) & 7;
        int u2  = i >> 8;
        int c = u2 & 3, g = u2 >> 2;
        int k = s * 8 + c + 4 * j;
        int n = ntg * 8 + g;
        float v = (k < GDIM) ? Wf1[k * FDIM + n] : 0.0f;
        g_B1img[u2 * RB1 + s * 32 + ntg * 2 + j] = to_tf32(v);
    }
#pragma unroll 1
    for (int i = t; i < 32 * 16 * 16 * 2; i += stride) {
        int j   = i & 1;
        int ntg = (i >> 1) & 15;
        int s   = (i >> 5) & 15;
        int u2  = i >> 9;
        int c = u2 & 3, g = u2 >> 2;
        int k = s * 8 + c + 4 * j;
        int n = ntg * 8 + g;
        g_B2img[u2 * RB2 + s * 32 + ntg * 2 + j] = to_tf32(Wf2[k * FDIM + n]);
    }
}

// ---------------------------------------------------------------------------
// k_in2f: g_y = x @ Win (FFMA2)
// ---------------------------------------------------------------------------
__global__ __launch_bounds__(256) void k_in2f(const float* __restrict__ x,
                                              const float* __restrict__ Win) {
    extern __shared__ float sm[];
    float* Ws = sm;
    float* xs = sm + FDIM * FDIM;
    const int t = threadIdx.x;
    const int row0 = blockIdx.x * 16;
    for (int i = t * 4; i < FDIM * FDIM; i += 1024)
        *(float4*)(Ws + i) = *(const float4*)(Win + i);
    for (int i = t * 4; i < 16 * FDIM; i += 1024) {
        int r = i >> 7, c = i & 127;
        *(float4*)(xs + r * H1S + c) = *(const float4*)(x + (row0 + r) * FDIM + c);
    }
    __syncthreads();
    const int r = t >> 4;
    const int c0 = (t & 15) * 8;
    u64 acc[4] = {0, 0, 0, 0};
#pragma unroll 4
    for (int d = 0; d < FDIM; d++) {
        u64 a2 = pk2(xs[r * H1S + d], xs[r * H1S + d]);
        const u64* wp = (const u64*)(Ws + d * FDIM + c0);
#pragma unroll
        for (int j = 0; j < 4; j++) acc[j] = fma2(a2, wp[j], acc[j]);
    }
    u64* o = (u64*)(g_y + (row0 + r) * FDIM + c0);
#pragma unroll
    for (int j = 0; j < 4; j++) o[j] = acc[j];
}

// ---------------------------------------------------------------------------
// k_main: tf32 mma.sync fused filter-net + gather + masked aggregate.
// grid MAIN_GRID x 512. 16 warps = 4 wrow x 4 wcol; warp tile 32 rows x 32 cols.
// ---------------------------------------------------------------------------
__global__ __launch_bounds__(512, 1) void k_main(const float* __restrict__ f_ij,
                                                 const int* __restrict__ neighbors,
                                                 const float* __restrict__ pmask,
                                                 const float* __restrict__ bf1,
                                                 const float* __restrict__ bf2) {
    extern __shared__ float sm[];
    const int t = threadIdx.x;
    const int w = t >> 5, lane = t & 31;
    const int g = lane >> 2, c = lane & 3;
    const int wrow = w >> 2, wcol = w & 3;

    float* bf1s  = sm + O_BF1;
    float* bf2s  = sm + O_BF2;
    float* masks = sm + O_MASK;
    int*   nbrs  = (int*)(sm + O_NBR);
    float* red   = sm + O_RED;

    // one-time: weight fragments + biases
    for (int i = t * 2; i < 32 * RB1; i += 1024)
        *(float2*)(sm + O_B1 + i) = *(const float2*)(g_B1img + i);
    for (int i = t * 2; i < 32 * RB2; i += 1024)
        *(float2*)(sm + O_B2 + i) = *(const float2*)(g_B2img + i);
    if (t < FDIM) { bf1s[t] = bf1[t]; bf2s[t] = bf2[t]; }
    __syncthreads();

#pragma unroll 1
    for (int rep = 0; rep < BN_PER_CTA; rep++) {
        const int bn = blockIdx.x * BN_PER_CTA + rep;
        const int b  = bn >> 8;
        const float* fb = f_ij + (long)bn * (NBHC * GDIM);

        float acc[8];
#pragma unroll
        for (int j = 0; j < 8; j++) acc[j] = 0.0f;

#pragma unroll 1
        for (int ch = 0; ch < 2; ch++) {
            __syncthreads();   // prior consumers of A1/A2/mask done

            // ---- stage A1 chunk (128 rows x 64 k, fragment-permuted, tf32) ----
#pragma unroll 1
            for (int i = t; i < 128 * 64; i += 512) {
                int row = i >> 6, k = i & 63;
                int grow = ch * 128 + row;
                float v = (k < GDIM && grow < NBHC) ? fb[grow * GDIM + k] : 0.0f;
                sm[O_A1 + (row >> 4) * A1_TILE +
                   (((row & 15) << 2) + (k & 3)) * K1P + (k >> 2)] = to_tf32(v);
            }
            if (t < 128) {
                int grow = ch * 128 + t;
                masks[t] = (grow < NBHC) ? pmask[bn * NBHC + grow] : 0.0f;
                nbrs[t]  = (grow < NBHC) ? neighbors[bn * NBHC + grow] : 0;
            }
            __syncthreads();

            // ---- GEMM1: C1 = A1 @ B1 (K=64) ----
            float C1[2][4][4];
#pragma unroll
            for (int mt = 0; mt < 2; mt++)
#pragma unroll
                for (int nt = 0; nt < 4; nt++)
#pragma unroll
                    for (int q = 0; q < 4; q++) C1[mt][nt][q] = 0.0f;

#pragma unroll
            for (int s = 0; s < 8; s++) {
                float2 alo[2], ahi[2];
#pragma unroll
                for (int mt = 0; mt < 2; mt++) {
                    const float* tile = sm + O_A1 + (wrow * 2 + mt) * A1_TILE;
                    alo[mt] = *(const float2*)(tile + lane * K1P + 2 * s);
                    ahi[mt] = *(const float2*)(tile + (lane + 32) * K1P + 2 * s);
                }
                const float* brow = sm + O_B1 + lane * RB1 + s * 32 + wcol * 8;
                float2 bf[4];
#pragma unroll
                for (int nt = 0; nt < 4; nt++) bf[nt] = *(const float2*)(brow + nt * 2);
#pragma unroll
                for (int nt = 0; nt < 4; nt++)
#pragma unroll
                    for (int mt = 0; mt < 2; mt++)
                        mma8(C1[mt][nt], alo[mt], ahi[mt], bf[nt]);
            }

            // ---- epilogue 1: bias + ssp -> A2 fragment-permuted (tf32) ----
#pragma unroll
            for (int mt = 0; mt < 2; mt++) {
                float* a2t = sm + O_A2 + (wrow * 2 + mt) * A2_TILE;
#pragma unroll
                for (int nt = 0; nt < 4; nt++) {
                    int col = wcol * 32 + nt * 8 + 2 * c;
                    float h0 = to_tf32(sspf(C1[mt][nt][0] + bf1s[col]));
                    float h1 = to_tf32(sspf(C1[mt][nt][1] + bf1s[col + 1]));
                    float h2 = to_tf32(sspf(C1[mt][nt][2] + bf1s[col]));
                    float h3 = to_tf32(sspf(C1[mt][nt][3] + bf1s[col + 1]));
                    int u0 = (g << 2)       + (col & 3);
                    int u1 = (g << 2)       + ((col + 1) & 3);
                    int u2 = ((g + 8) << 2) + (col & 3);
                    int u3 = ((g + 8) << 2) + ((col + 1) & 3);
                    a2t[u0 * K2P + (col >> 2)]       = h0;
                    a2t[u1 * K2P + ((col + 1) >> 2)] = h1;
                    a2t[u2 * K2P + (col >> 2)]       = h2;
                    a2t[u3 * K2P + ((col + 1) >> 2)] = h3;
                }
            }
            __syncthreads();

            // ---- GEMM2: C2 = A2 @ B2 (K=128) ----
            float C2[2][4][4];
#pragma unroll
            for (int mt = 0; mt < 2; mt++)
#pragma unroll
                for (int nt = 0; nt < 4; nt++)
#pragma unroll
                    for (int q = 0; q < 4; q++) C2[mt][nt][q] = 0.0f;

#pragma unroll
            for (int s = 0; s < 16; s++) {
                float2 alo[2], ahi[2];
#pragma unroll
                for (int mt = 0; mt < 2; mt++) {
                    const float* tile = sm + O_A2 + (wrow * 2 + mt) * A2_TILE;
                    alo[mt] = *(const float2*)(tile + lane * K2P + 2 * s);
                    ahi[mt] = *(const float2*)(tile + (lane + 32) * K2P + 2 * s);
                }
                const float* brow = sm + O_B2 + lane * RB2 + s * 32 + wcol * 8;
                float2 bf[4];
#pragma unroll
                for (int nt = 0; nt < 4; nt++) bf[nt] = *(const float2*)(brow + nt * 2);
#pragma unroll
                for (int nt = 0; nt < 4; nt++)
#pragma unroll
                    for (int mt = 0; mt < 2; mt++)
                        mma8(C2[mt][nt], alo[mt], ahi[mt], bf[nt]);
            }

            // ---- epilogue 2: bias, mask, gather y[nbr], accumulate ----
#pragma unroll
            for (int mt = 0; mt < 2; mt++) {
                int r0 = wrow * 32 + mt * 16 + g;
                float m0 = masks[r0], m1 = masks[r0 + 8];
                int   n0 = nbrs[r0],  n1 = nbrs[r0 + 8];
                const float* y0 = g_y + ((((b << 8) + n0)) << 7);
                const float* y1 = g_y + ((((b << 8) + n1)) << 7);
#pragma unroll
                for (int nt = 0; nt < 4; nt++) {
                    int col = wcol * 32 + nt * 8 + 2 * c;
                    float2 yv0 = *(const float2*)(y0 + col);
                    float2 yv1 = *(const float2*)(y1 + col);
                    float w00 = C2[mt][nt][0] + bf2s[col];
                    float w01 = C2[mt][nt][1] + bf2s[col + 1];
                    float w10 = C2[mt][nt][2] + bf2s[col];
                    float w11 = C2[mt][nt][3] + bf2s[col + 1];
                    acc[nt * 2]     = fmaf(m0 * w00, yv0.x, fmaf(m1 * w10, yv1.x, acc[nt * 2]));
                    acc[nt * 2 + 1] = fmaf(m0 * w01, yv0.y, fmaf(m1 * w11, yv1.y, acc[nt * 2 + 1]));
                }
            }
        }

        // ---- reduce over g (lanes stride-4) then over wrow warps via smem ----
#pragma unroll
        for (int j = 0; j < 8; j++) {
            float v = acc[j];
            v += __shfl_xor_sync(0xffffffffu, v, 4);
            v += __shfl_xor_sync(0xffffffffu, v, 8);
            v += __shfl_xor_sync(0xffffffffu, v, 16);
            acc[j] = v;
        }
        __syncthreads();   // red region (fresh each rep)
        if (g == 0) {
#pragma unroll
            for (int nt = 0; nt < 4; nt++) {
                int col = wcol * 32 + nt * 8 + 2 * c;
                red[wrow * FDIM + col]     = acc[nt * 2];
                red[wrow * FDIM + col + 1] = acc[nt * 2 + 1];
            }
        }
        __syncthreads();
        if (t < FDIM) {
            g_ypre[bn * FDIM + t] =
                red[t] + red[FDIM + t] + red[2 * FDIM + t] + red[3 * FDIM + t];
        }
    }
}

// ---------------------------------------------------------------------------
// k_out: out = ssp(g_ypre @ Wout + bout) (FFMA2)
// ---------------------------------------------------------------------------
__global__ __launch_bounds__(256) void k_out(const float* __restrict__ Wout,
                                             const float* __restrict__ bout,
                                             float* __restrict__ out) {
    extern __shared__ float sm[];
    float* Ws = sm;
    float* xs = Ws + FDIM * FDIM;
    float* bs = xs + 16 * H1S;
    const int t = threadIdx.x;
    const int row0 = blockIdx.x * 16;
    for (int i = t * 4; i < FDIM * FDIM; i += 1024)
        *(float4*)(Ws + i) = *(const float4*)(Wout + i);
    for (int i = t * 4; i < 16 * FDIM; i += 1024) {
        int r = i >> 7, c = i & 127;
        *(float4*)(xs + r * H1S + c) = *(const float4*)(g_ypre + (row0 + r) * FDIM + c);
    }
    if (t < FDIM) bs[t] = bout[t];
    __syncthreads();
    const int r = t >> 4;
    const int c0 = (t & 15) * 8;
    u64 acc[4];
#pragma unroll
    for (int j = 0; j < 4; j++) acc[j] = pk2(bs[c0 + 2 * j], bs[c0 + 2 * j + 1]);
#pragma unroll 4
    for (int d = 0; d < FDIM; d++) {
        u64 a2 = pk2(xs[r * H1S + d], xs[r * H1S + d]);
        const u64* wp = (const u64*)(Ws + d * FDIM + c0);
#pragma unroll
        for (int j = 0; j < 4; j++) acc[j] = fma2(a2, wp[j], acc[j]);
    }
    float* o = out + (row0 + r) * FDIM + c0;
#pragma unroll
    for (int j = 0; j < 4; j++) {
        float lo, hi;
        upk2(acc[j], lo, hi);
        o[2 * j]     = sspf(lo);
        o[2 * j + 1] = sspf(hi);
    }
}

// ---------------------------------------------------------------------------
extern "C" void kernel_launch(void* const* d_in, const int* in_sizes, int n_in,
                              void* d_out, int out_size) {
    const float* x         = (const float*)d_in[0];
    const int*   neighbors = (const int*)d_in[2];
    const float* pmask     = (const float*)d_in[3];
    const float* f_ij      = (const float*)d_in[4];
    const float* Wf1       = (const float*)d_in[5];
    const float* bf1       = (const float*)d_in[6];
    const float* Wf2       = (const float*)d_in[7];
    const float* bf2       = (const float*)d_in[8];
    const float* Win       = (const float*)d_in[9];
    const float* Wout      = (const float*)d_in[10];
    const float* bout      = (const float*)d_in[11];

    const int smem1 = (FDIM * FDIM + 16 * H1S) * 4;
    const int smem3 = (FDIM * FDIM + 16 * H1S + FDIM) * 4;

    cudaFuncSetAttribute(k_in2f, cudaFuncAttributeMaxDynamicSharedMemorySize, smem1);
    cudaFuncSetAttribute(k_main, cudaFuncAttributeMaxDynamicSharedMemorySize, SMEM_MAIN);
    cudaFuncSetAttribute(k_out,  cudaFuncAttributeMaxDynamicSharedMemorySize, smem3);

    k_prep<<<32, 256>>>(Wf1, Wf2);
    k_in2f<<<BN_TOTAL / 16, 256, smem1>>>(x, Win);
    k_main<<<MAIN_GRID, 512, SMEM_MAIN>>>(f_ij, neighbors, pmask, bf1, bf2);
    k_out<<<BN_TOTAL / 16, 256, smem3>>>(Wout, bout, (float*)d_out);
}

// round 11
// speedup vs baseline: 2.7055x; 1.3077x over previous
#include <cuda_runtime.h>
#include <cstdint>

// CFConv (SchNet): mma.sync tf32 fused kernel, 1024-thread k_main (32 warps).
// Shapes: B=16, N=256, NBH=255, G=50, F=128.
// d_in: 0:x 1:r_ij(unused) 2:neighbors 3:pairwise_mask 4:f_ij
//       5:Wf1 6:bf1 7:Wf2 8:bf2 9:Win 10:Wout 11:bout

#define BN_TOTAL 4096
#define FDIM 128
#define GDIM 50
#define NBHC 255
#define H1S 132
#define BN_PER_CTA 4
#define MAIN_GRID (BN_TOTAL / BN_PER_CTA)

// fragment-permuted A layouts: per 16-row tile, u = row16*4 + (k&3), kk = k>>2
#define K1P 18                    // GEMM1: 16 kk + 2 pad (K=64)
#define A1_TILE (64 * K1P)        // 1152 floats
#define K2P 34                    // GEMM2: 32 kk + 2 pad (K=128)
#define A2_TILE (64 * K2P)        // 2176 floats
#define RB1 258                   // B1 per-thread row: 8 s * 32 + 2 pad
#define RB2 514                   // B2 per-thread row: 16 s * 32 + 2 pad

// float offsets in k_main smem
#define O_A1   0
#define O_A2   (O_A1 + 8 * A1_TILE)     // 9216
#define O_B1   (O_A2 + 8 * A2_TILE)     // 26624
#define O_B2   (O_B1 + 32 * RB1)        // 34880
#define O_BF1  (O_B2 + 32 * RB2)        // 51328
#define O_BF2  (O_BF1 + 128)
#define O_MASK (O_BF2 + 128)
#define O_NBR  (O_MASK + 128)
#define O_RED  (O_NBR + 128)
#define SMEM_MAIN ((O_RED + 1024) * 4)  // 211456 B

typedef unsigned long long u64;

__device__ float g_y[BN_TOTAL * FDIM];
__device__ float g_ypre[BN_TOTAL * FDIM];
__device__ float g_B1img[32 * RB1];     // Wf1 fragment-permuted (tf32)
__device__ float g_B2img[32 * RB2];     // Wf2 fragment-permuted (tf32)

// fast shifted-softplus: ln(1+e^v) - ln2, via MUFU ex2/lg2 (err ~1e-7 abs)
__device__ __forceinline__ float sspf(float v) {
    float e = __expf(-fabsf(v));
    return fmaxf(v, 0.0f) + 0.69314718055994531f * __log2f(1.0f + e)
           - 0.69314718055994531f;
}
// tf32 cvt: destination must be a .b32 register (ptxas rejects .f32 dst).
__device__ __forceinline__ float to_tf32(float v) {
    uint32_t r; asm("cvt.rna.tf32.f32 %0, %1;" : "=r"(r) : "f"(v));
    return __uint_as_float(r);
}

// ---- packed f32x2 helpers (small kernels) ----
__device__ __forceinline__ u64 pk2(float lo, float hi) {
    u64 r; asm("mov.b64 %0, {%1, %2};" : "=l"(r) : "f"(lo), "f"(hi)); return r;
}
__device__ __forceinline__ void upk2(u64 v, float& lo, float& hi) {
    asm("mov.b64 {%0, %1}, %2;" : "=f"(lo), "=f"(hi) : "l"(v));
}
__device__ __forceinline__ u64 fma2(u64 a, u64 b, u64 c) {
    u64 d; asm("fma.rn.f32x2 %0, %1, %2, %3;" : "=l"(d) : "l"(a), "l"(b), "l"(c)); return d;
}

// m16n8k8 tf32 MMA. a0=(g,c) a1=(g+8,c) a2=(g,c+4) a3=(g+8,c+4); b0=(c,g) b1=(c+4,g)
__device__ __forceinline__ void mma8(float d[4], float2 alo, float2 ahi, float2 b) {
    asm volatile(
        "mma.sync.aligned.m16n8k8.row.col.f32.tf32.tf32.f32 "
        "{%0,%1,%2,%3}, {%4,%5,%6,%7}, {%8,%9}, {%0,%1,%2,%3};"
        : "+f"(d[0]), "+f"(d[1]), "+f"(d[2]), "+f"(d[3])
        : "r"(__float_as_uint(alo.x)), "r"(__float_as_uint(ahi.x)),
          "r"(__float_as_uint(alo.y)), "r"(__float_as_uint(ahi.y)),
          "r"(__float_as_uint(b.x)),   "r"(__float_as_uint(b.y)));
}

// ---------------------------------------------------------------------------
// k_prep: fragment-permute + tf32-round both filter weights into global images.
// ---------------------------------------------------------------------------
__global__ void k_prep(const float* __restrict__ Wf1, const float* __restrict__ Wf2) {
    int t = blockIdx.x * blockDim.x + threadIdx.x;
    int stride = gridDim.x * blockDim.x;
#pragma unroll 1
    for (int i = t; i < 32 * 8 * 16 * 2; i += stride) {
        int j   = i & 1;
        int ntg = (i >> 1) & 15;
        int s   = (i >> 5) & 7;
        int u2  = i >> 8;
        int c = u2 & 3, g = u2 >> 2;
        int k = s * 8 + c + 4 * j;
        int n = ntg * 8 + g;
        float v = (k < GDIM) ? Wf1[k * FDIM + n] : 0.0f;
        g_B1img[u2 * RB1 + s * 32 + ntg * 2 + j] = to_tf32(v);
    }
#pragma unroll 1
    for (int i = t; i < 32 * 16 * 16 * 2; i += stride) {
        int j   = i & 1;
        int ntg = (i >> 1) & 15;
        int s   = (i >> 5) & 15;
        int u2  = i >> 9;
        int c = u2 & 3, g = u2 >> 2;
        int k = s * 8 + c + 4 * j;
        int n = ntg * 8 + g;
        g_B2img[u2 * RB2 + s * 32 + ntg * 2 + j] = to_tf32(Wf2[k * FDIM + n]);
    }
}

// ---------------------------------------------------------------------------
// k_in2f: g_y = x @ Win (FFMA2)
// ---------------------------------------------------------------------------
__global__ __launch_bounds__(256) void k_in2f(const float* __restrict__ x,
                                              const float* __restrict__ Win) {
    extern __shared__ float sm[];
    float* Ws = sm;
    float* xs = sm + FDIM * FDIM;
    const int t = threadIdx.x;
    const int row0 = blockIdx.x * 16;
    for (int i = t * 4; i < FDIM * FDIM; i += 1024)
        *(float4*)(Ws + i) = *(const float4*)(Win + i);
    for (int i = t * 4; i < 16 * FDIM; i += 1024) {
        int r = i >> 7, c = i & 127;
        *(float4*)(xs + r * H1S + c) = *(const float4*)(x + (row0 + r) * FDIM + c);
    }
    __syncthreads();
    const int r = t >> 4;
    const int c0 = (t & 15) * 8;
    u64 acc[4] = {0, 0, 0, 0};
#pragma unroll 4
    for (int d = 0; d < FDIM; d++) {
        u64 a2 = pk2(xs[r * H1S + d], xs[r * H1S + d]);
        const u64* wp = (const u64*)(Ws + d * FDIM + c0);
#pragma unroll
        for (int j = 0; j < 4; j++) acc[j] = fma2(a2, wp[j], acc[j]);
    }
    u64* o = (u64*)(g_y + (row0 + r) * FDIM + c0);
#pragma unroll
    for (int j = 0; j < 4; j++) o[j] = acc[j];
}

// ---------------------------------------------------------------------------
// k_main: tf32 mma.sync fused filter-net + gather + masked aggregate.
// grid MAIN_GRID x 1024. 32 warps = 8 wrow x 4 wcol; warp tile 16 rows x 32 cols.
// ---------------------------------------------------------------------------
__global__ __launch_bounds__(1024, 1) void k_main(const float* __restrict__ f_ij,
                                                  const int* __restrict__ neighbors,
                                                  const float* __restrict__ pmask,
                                                  const float* __restrict__ bf1,
                                                  const float* __restrict__ bf2) {
    extern __shared__ float sm[];
    const int t = threadIdx.x;
    const int w = t >> 5, lane = t & 31;
    const int g = lane >> 2, c = lane & 3;
    const int wrow = w >> 2, wcol = w & 3;

    float* bf1s  = sm + O_BF1;
    float* bf2s  = sm + O_BF2;
    float* masks = sm + O_MASK;
    int*   nbrs  = (int*)(sm + O_NBR);
    float* red   = sm + O_RED;

    // one-time: weight fragments + biases
    for (int i = t * 2; i < 32 * RB1; i += 2048)
        *(float2*)(sm + O_B1 + i) = *(const float2*)(g_B1img + i);
    for (int i = t * 2; i < 32 * RB2; i += 2048)
        *(float2*)(sm + O_B2 + i) = *(const float2*)(g_B2img + i);
    if (t < FDIM) { bf1s[t] = bf1[t]; bf2s[t] = bf2[t]; }
    __syncthreads();

#pragma unroll 1
    for (int rep = 0; rep < BN_PER_CTA; rep++) {
        const int bn = blockIdx.x * BN_PER_CTA + rep;
        const int b  = bn >> 8;
        const float* fb = f_ij + (long)bn * (NBHC * GDIM);

        float acc[8];
#pragma unroll
        for (int j = 0; j < 8; j++) acc[j] = 0.0f;

#pragma unroll 1
        for (int ch = 0; ch < 2; ch++) {
            __syncthreads();   // prior consumers of A1/A2/mask done

            // ---- stage A1 chunk (128 rows x 64 k, fragment-permuted, tf32) ----
#pragma unroll 1
            for (int i = t; i < 128 * 64; i += 1024) {
                int row = i >> 6, k = i & 63;
                int grow = ch * 128 + row;
                float v = (k < GDIM && grow < NBHC) ? fb[grow * GDIM + k] : 0.0f;
                sm[O_A1 + (row >> 4) * A1_TILE +
                   (((row & 15) << 2) + (k & 3)) * K1P + (k >> 2)] = to_tf32(v);
            }
            if (t < 128) {
                int grow = ch * 128 + t;
                masks[t] = (grow < NBHC) ? pmask[bn * NBHC + grow] : 0.0f;
                nbrs[t]  = (grow < NBHC) ? neighbors[bn * NBHC + grow] : 0;
            }
            __syncthreads();

            // ---- GEMM1: C1 = A1 @ B1 (K=64), warp tile 16x32 ----
            float C1[4][4];
#pragma unroll
            for (int nt = 0; nt < 4; nt++)
#pragma unroll
                for (int q = 0; q < 4; q++) C1[nt][q] = 0.0f;

#pragma unroll
            for (int s = 0; s < 8; s++) {
                const float* tile = sm + O_A1 + wrow * A1_TILE;
                float2 alo = *(const float2*)(tile + lane * K1P + 2 * s);
                float2 ahi = *(const float2*)(tile + (lane + 32) * K1P + 2 * s);
                const float* brow = sm + O_B1 + lane * RB1 + s * 32 + wcol * 8;
                float2 bf[4];
#pragma unroll
                for (int nt = 0; nt < 4; nt++) bf[nt] = *(const float2*)(brow + nt * 2);
#pragma unroll
                for (int nt = 0; nt < 4; nt++)
                    mma8(C1[nt], alo, ahi, bf[nt]);
            }

            // ---- epilogue 1: bias + ssp -> A2 fragment-permuted (tf32) ----
            {
                float* a2t = sm + O_A2 + wrow * A2_TILE;
#pragma unroll
                for (int nt = 0; nt < 4; nt++) {
                    int col = wcol * 32 + nt * 8 + 2 * c;
                    float h0 = to_tf32(sspf(C1[nt][0] + bf1s[col]));
                    float h1 = to_tf32(sspf(C1[nt][1] + bf1s[col + 1]));
                    float h2 = to_tf32(sspf(C1[nt][2] + bf1s[col]));
                    float h3 = to_tf32(sspf(C1[nt][3] + bf1s[col + 1]));
                    int u0 = (g << 2)       + (col & 3);
                    int u1 = (g << 2)       + ((col + 1) & 3);
                    int u2 = ((g + 8) << 2) + (col & 3);
                    int u3 = ((g + 8) << 2) + ((col + 1) & 3);
                    a2t[u0 * K2P + (col >> 2)]       = h0;
                    a2t[u1 * K2P + ((col + 1) >> 2)] = h1;
                    a2t[u2 * K2P + (col >> 2)]       = h2;
                    a2t[u3 * K2P + ((col + 1) >> 2)] = h3;
                }
            }
            __syncthreads();

            // ---- GEMM2: C2 = A2 @ B2 (K=128) ----
            float C2[4][4];
#pragma unroll
            for (int nt = 0; nt < 4; nt++)
#pragma unroll
                for (int q = 0; q < 4; q++) C2[nt][q] = 0.0f;

#pragma unroll
            for (int s = 0; s < 16; s++) {
                const float* tile = sm + O_A2 + wrow * A2_TILE;
                float2 alo = *(const float2*)(tile + lane * K2P + 2 * s);
                float2 ahi = *(const float2*)(tile + (lane + 32) * K2P + 2 * s);
                const float* brow = sm + O_B2 + lane * RB2 + s * 32 + wcol * 8;
                float2 bf[4];
#pragma unroll
                for (int nt = 0; nt < 4; nt++) bf[nt] = *(const float2*)(brow + nt * 2);
#pragma unroll
                for (int nt = 0; nt < 4; nt++)
                    mma8(C2[nt], alo, ahi, bf[nt]);
            }

            // ---- epilogue 2: bias, mask, gather y[nbr], accumulate ----
            {
                int r0 = wrow * 16 + g;
                float m0 = masks[r0], m1 = masks[r0 + 8];
                int   n0 = nbrs[r0],  n1 = nbrs[r0 + 8];
                const float* y0 = g_y + ((((b << 8) + n0)) << 7);
                const float* y1 = g_y + ((((b << 8) + n1)) << 7);
#pragma unroll
                for (int nt = 0; nt < 4; nt++) {
                    int col = wcol * 32 + nt * 8 + 2 * c;
                    float2 yv0 = *(const float2*)(y0 + col);
                    float2 yv1 = *(const float2*)(y1 + col);
                    float w00 = C2[nt][0] + bf2s[col];
                    float w01 = C2[nt][1] + bf2s[col + 1];
                    float w10 = C2[nt][2] + bf2s[col];
                    float w11 = C2[nt][3] + bf2s[col + 1];
                    acc[nt * 2]     = fmaf(m0 * w00, yv0.x, fmaf(m1 * w10, yv1.x, acc[nt * 2]));
                    acc[nt * 2 + 1] = fmaf(m0 * w01, yv0.y, fmaf(m1 * w11, yv1.y, acc[nt * 2 + 1]));
                }
            }
        }

        // ---- reduce over g (lanes stride-4) then over 8 wrow warps via smem ----
#pragma unroll
        for (int j = 0; j < 8; j++) {
            float v = acc[j];
            v += __shfl_xor_sync(0xffffffffu, v, 4);
            v += __shfl_xor_sync(0xffffffffu, v, 8);
            v += __shfl_xor_sync(0xffffffffu, v, 16);
            acc[j] = v;
        }
        __syncthreads();   // red region (fresh each rep)
        if (g == 0) {
#pragma unroll
            for (int nt = 0; nt < 4; nt++) {
                int col = wcol * 32 + nt * 8 + 2 * c;
                red[wrow * FDIM + col]     = acc[nt * 2];
                red[wrow * FDIM + col + 1] = acc[nt * 2 + 1];
            }
        }
        __syncthreads();
        if (t < FDIM) {
            float s = 0.0f;
#pragma unroll
            for (int i = 0; i < 8; i++) s += red[i * FDIM + t];
            g_ypre[bn * FDIM + t] = s;
        }
    }
}

// ---------------------------------------------------------------------------
// k_out: out = ssp(g_ypre @ Wout + bout) (FFMA2)
// ---------------------------------------------------------------------------
__global__ __launch_bounds__(256) void k_out(const float* __restrict__ Wout,
                                             const float* __restrict__ bout,
                                             float* __restrict__ out) {
    extern __shared__ float sm[];
    float* Ws = sm;
    float* xs = Ws + FDIM * FDIM;
    float* bs = xs + 16 * H1S;
    const int t = threadIdx.x;
    const int row0 = blockIdx.x * 16;
    for (int i = t * 4; i < FDIM * FDIM; i += 1024)
        *(float4*)(Ws + i) = *(const float4*)(Wout + i);
    for (int i = t * 4; i < 16 * FDIM; i += 1024) {
        int r = i >> 7, c = i & 127;
        *(float4*)(xs + r * H1S + c) = *(const float4*)(g_ypre + (row0 + r) * FDIM + c);
    }
    if (t < FDIM) bs[t] = bout[t];
    __syncthreads();
    const int r = t >> 4;
    const int c0 = (t & 15) * 8;
    u64 acc[4];
#pragma unroll
    for (int j = 0; j < 4; j++) acc[j] = pk2(bs[c0 + 2 * j], bs[c0 + 2 * j + 1]);
#pragma unroll 4
    for (int d = 0; d < FDIM; d++) {
        u64 a2 = pk2(xs[r * H1S + d], xs[r * H1S + d]);
        const u64* wp = (const u64*)(Ws + d * FDIM + c0);
#pragma unroll
        for (int j = 0; j < 4; j++) acc[j] = fma2(a2, wp[j], acc[j]);
    }
    float* o = out + (row0 + r) * FDIM + c0;
#pragma unroll
    for (int j = 0; j < 4; j++) {
        float lo, hi;
        upk2(acc[j], lo, hi);
        o[2 * j]     = sspf(lo);
        o[2 * j + 1] = sspf(hi);
    }
}

// ---------------------------------------------------------------------------
extern "C" void kernel_launch(void* const* d_in, const int* in_sizes, int n_in,
                              void* d_out, int out_size) {
    const float* x         = (const float*)d_in[0];
    const int*   neighbors = (const int*)d_in[2];
    const float* pmask     = (const float*)d_in[3];
    const float* f_ij      = (const float*)d_in[4];
    const float* Wf1       = (const float*)d_in[5];
    const float* bf1       = (const float*)d_in[6];
    const float* Wf2       = (const float*)d_in[7];
    const float* bf2       = (const float*)d_in[8];
    const float* Win       = (const float*)d_in[9];
    const float* Wout      = (const float*)d_in[10];
    const float* bout      = (const float*)d_in[11];

    const int smem1 = (FDIM * FDIM + 16 * H1S) * 4;
    const int smem3 = (FDIM * FDIM + 16 * H1S + FDIM) * 4;

    cudaFuncSetAttribute(k_in2f, cudaFuncAttributeMaxDynamicSharedMemorySize, smem1);
    cudaFuncSetAttribute(k_main, cudaFuncAttributeMaxDynamicSharedMemorySize, SMEM_MAIN);
    cudaFuncSetAttribute(k_out,  cudaFuncAttributeMaxDynamicSharedMemorySize, smem3);

    k_prep<<<32, 256>>>(Wf1, Wf2);
    k_in2f<<<BN_TOTAL / 16, 256, smem1>>>(x, Win);
    k_main<<<MAIN_GRID, 1024, SMEM_MAIN>>>(f_ij, neighbors, pmask, bf1, bf2);
    k_out<<<BN_TOTAL / 16, 256, smem3>>>(Wout, bout, (float*)d_out);
}